// round 1
// baseline (speedup 1.0000x reference)
#include <cuda_runtime.h>
#include <cuda_bf16.h>
#include <cstdint>
#include <cstddef>

#define BATCH 8192
#define DIN   12288
#define HID   2048

// ---------------- static device scratch (no allocations allowed) ----------------
__device__ __nv_bfloat16 g_Xh [(size_t)BATCH * DIN];
__device__ __nv_bfloat16 g_Xl [(size_t)BATCH * DIN];
__device__ __nv_bfloat16 g_W1h[(size_t)DIN * HID];
__device__ __nv_bfloat16 g_W1l[(size_t)DIN * HID];
__device__ __nv_bfloat16 g_W2h[(size_t)HID * HID];
__device__ __nv_bfloat16 g_W2l[(size_t)HID * HID];
__device__ __nv_bfloat16 g_W3h[(size_t)HID * DIN];
__device__ __nv_bfloat16 g_H1h[(size_t)BATCH * HID];
__device__ __nv_bfloat16 g_H1l[(size_t)BATCH * HID];
__device__ float         g_H2 [(size_t)BATCH * HID];
__device__ __nv_bfloat16 g_H2s[(size_t)BATCH * HID];

// ---------------- helpers ----------------
__device__ __forceinline__ unsigned sptr(const void* p) {
    return (unsigned)__cvta_generic_to_shared(p);
}
__device__ __forceinline__ void ldsm4(unsigned &r0, unsigned &r1, unsigned &r2, unsigned &r3, unsigned a) {
    asm volatile("ldmatrix.sync.aligned.m8n8.x4.shared.b16 {%0,%1,%2,%3}, [%4];\n"
                 : "=r"(r0), "=r"(r1), "=r"(r2), "=r"(r3) : "r"(a));
}
__device__ __forceinline__ void ldsm4t(unsigned &r0, unsigned &r1, unsigned &r2, unsigned &r3, unsigned a) {
    asm volatile("ldmatrix.sync.aligned.m8n8.x4.trans.shared.b16 {%0,%1,%2,%3}, [%4];\n"
                 : "=r"(r0), "=r"(r1), "=r"(r2), "=r"(r3) : "r"(a));
}
__device__ __forceinline__ void mma16816(float* d, const unsigned* a, const unsigned* b) {
    asm volatile("mma.sync.aligned.m16n8k16.row.col.f32.bf16.bf16.f32 "
                 "{%0,%1,%2,%3}, {%4,%5,%6,%7}, {%8,%9}, {%0,%1,%2,%3};\n"
                 : "+f"(d[0]), "+f"(d[1]), "+f"(d[2]), "+f"(d[3])
                 : "r"(a[0]), "r"(a[1]), "r"(a[2]), "r"(a[3]), "r"(b[0]), "r"(b[1]));
}

// ---------------- fp32 -> bf16 (hi, lo) split ----------------
template<bool HASLO>
__global__ void split_kernel(const float4* __restrict__ in,
                             __nv_bfloat162* __restrict__ hi,
                             __nv_bfloat162* __restrict__ lo, int n4) {
    int stride = gridDim.x * blockDim.x;
    for (int i = blockIdx.x * blockDim.x + threadIdx.x; i < n4; i += stride) {
        float4 v = in[i];
        __nv_bfloat16 h0 = __float2bfloat16(v.x), h1 = __float2bfloat16(v.y);
        __nv_bfloat16 h2 = __float2bfloat16(v.z), h3 = __float2bfloat16(v.w);
        __nv_bfloat162 a; a.x = h0; a.y = h1;
        __nv_bfloat162 b; b.x = h2; b.y = h3;
        hi[2 * i] = a; hi[2 * i + 1] = b;
        if (HASLO) {
            __nv_bfloat162 c, d;
            c.x = __float2bfloat16(v.x - __bfloat162float(h0));
            c.y = __float2bfloat16(v.y - __bfloat162float(h1));
            d.x = __float2bfloat16(v.z - __bfloat162float(h2));
            d.y = __float2bfloat16(v.w - __bfloat162float(h3));
            lo[2 * i] = c; lo[2 * i + 1] = d;
        }
    }
}

// ---------------- GEMM: C[M,N] = A[M,K] * B[K,N] (+bias, epilogue) ----------------
// SPLIT==3: A,B given as (hi,lo); accumulate Ah*Bh + Ah*Bl + Al*Bh  (Ootomo split)
// SPLIT==1: plain bf16 (Al/Bl unused)
// EPI: 0 = relu -> write (hi,lo) bf16 split; 1 = plain fp32; 2 = sigmoid fp32
template<int SPLIT, int EPI>
__global__ void __launch_bounds__(256)
gemm_bf16(const __nv_bfloat16* __restrict__ Ah, const __nv_bfloat16* __restrict__ Al,
          const __nv_bfloat16* __restrict__ Bh, const __nv_bfloat16* __restrict__ Bl,
          const float* __restrict__ bias, int M, int N, int K,
          float* __restrict__ outF, __nv_bfloat16* __restrict__ outH, __nv_bfloat16* __restrict__ outL)
{
    constexpr int AP = 128 * 40;      // A part elems (32 cols + 8 pad per row)
    constexpr int BP = 32 * 136;      // B part elems (128 cols + 8 pad per row)
    constexpr int PARTS = (SPLIT == 3) ? 2 : 1;
    constexpr int STAGE = (AP + BP) * PARTS;
    extern __shared__ __nv_bfloat16 smbuf[];

    const int tid  = threadIdx.x;
    const int bm   = blockIdx.y * 128;
    const int bn   = blockIdx.x * 128;
    const int lane = tid & 31;
    const int warp = tid >> 5;
    const int wm   = warp & 3;   // 4 warps along M (32 rows each)
    const int wn   = warp >> 2;  // 2 warps along N (64 cols each)

    float acc[2][8][4];
    #pragma unroll
    for (int i = 0; i < 2; i++)
        #pragma unroll
        for (int j = 0; j < 8; j++)
            #pragma unroll
            for (int k = 0; k < 4; k++) acc[i][j][k] = 0.f;

    auto cpA = [&](const __nv_bfloat16* src, __nv_bfloat16* dst, int k0) {
        #pragma unroll
        for (int i = 0; i < 2; i++) {
            int c = tid + i * 256;
            int row = c >> 2, seg = c & 3;
            unsigned d = sptr(dst + row * 40 + seg * 8);
            const __nv_bfloat16* g = src + (size_t)(bm + row) * K + (k0 + seg * 8);
            asm volatile("cp.async.cg.shared.global [%0], [%1], 16;\n" :: "r"(d), "l"(g));
        }
    };
    auto cpB = [&](const __nv_bfloat16* src, __nv_bfloat16* dst, int k0) {
        #pragma unroll
        for (int i = 0; i < 2; i++) {
            int c = tid + i * 256;
            int row = c >> 4, seg = c & 15;
            unsigned d = sptr(dst + row * 136 + seg * 8);
            const __nv_bfloat16* g = src + (size_t)(k0 + row) * N + (bn + seg * 8);
            asm volatile("cp.async.cg.shared.global [%0], [%1], 16;\n" :: "r"(d), "l"(g));
        }
    };
    auto issue = [&](int kt, int st) {
        int k0 = kt * 32;
        __nv_bfloat16* base = smbuf + (size_t)st * STAGE;
        cpA(Ah, base, k0);
        if (SPLIT == 3) cpA(Al, base + AP, k0);
        cpB(Bh, base + AP * PARTS, k0);
        if (SPLIT == 3) cpB(Bl, base + AP * PARTS + BP, k0);
    };

    const int KT = K / 32;
    issue(0, 0);
    asm volatile("cp.async.commit_group;\n" ::: "memory");

    for (int kt = 0; kt < KT; ++kt) {
        int st = kt & 1;
        if (kt + 1 < KT) {
            issue(kt + 1, st ^ 1);
            asm volatile("cp.async.commit_group;\n" ::: "memory");
            asm volatile("cp.async.wait_group 1;\n" ::: "memory");
        } else {
            asm volatile("cp.async.wait_group 0;\n" ::: "memory");
        }
        __syncthreads();

        __nv_bfloat16* base = smbuf + (size_t)st * STAGE;
        __nv_bfloat16* Ash = base;
        __nv_bfloat16* Asl = base + AP;
        __nv_bfloat16* Bsh = base + AP * PARTS;
        __nv_bfloat16* Bsl = Bsh + BP;

        #pragma unroll
        for (int p = 0; p < SPLIT; p++) {
            const __nv_bfloat16* Asp = (p == 2) ? Asl : Ash;
            const __nv_bfloat16* Bsp = (p == 1) ? Bsl : Bsh;
            #pragma unroll
            for (int ks = 0; ks < 2; ++ks) {
                unsigned a[2][4];
                #pragma unroll
                for (int mi = 0; mi < 2; mi++) {
                    const __nv_bfloat16* ap = Asp
                        + (size_t)(wm * 32 + mi * 16 + (lane & 15)) * 40
                        + ks * 16 + (lane >> 4) * 8;
                    ldsm4(a[mi][0], a[mi][1], a[mi][2], a[mi][3], sptr(ap));
                }
                unsigned b[8][2];
                #pragma unroll
                for (int np = 0; np < 4; np++) {
                    const __nv_bfloat16* bpt = Bsp
                        + (size_t)(ks * 16 + (lane & 7) + 8 * ((lane >> 3) & 1)) * 136
                        + wn * 64 + np * 16 + 8 * (lane >> 4);
                    unsigned r0, r1, r2, r3;
                    ldsm4t(r0, r1, r2, r3, sptr(bpt));
                    b[2 * np][0] = r0; b[2 * np][1] = r1;
                    b[2 * np + 1][0] = r2; b[2 * np + 1][1] = r3;
                }
                #pragma unroll
                for (int mi = 0; mi < 2; mi++)
                    #pragma unroll
                    for (int ni = 0; ni < 8; ni++)
                        mma16816(acc[mi][ni], a[mi], b[ni]);
            }
        }
        __syncthreads();
    }

    // epilogue
    #pragma unroll
    for (int mi = 0; mi < 2; mi++) {
        #pragma unroll
        for (int ni = 0; ni < 8; ni++) {
            int r = bm + wm * 32 + mi * 16 + (lane >> 2);
            int c = bn + wn * 64 + ni * 8 + (lane & 3) * 2;
            float bb0 = bias[c], bb1 = bias[c + 1];
            #pragma unroll
            for (int half = 0; half < 2; ++half) {
                int rr = r + half * 8;
                float v0 = acc[mi][ni][2 * half + 0] + bb0;
                float v1 = acc[mi][ni][2 * half + 1] + bb1;
                size_t off = (size_t)rr * N + c;
                if (EPI == 0) {
                    v0 = fmaxf(v0, 0.f); v1 = fmaxf(v1, 0.f);
                    __nv_bfloat162 h; h.x = __float2bfloat16(v0); h.y = __float2bfloat16(v1);
                    *reinterpret_cast<__nv_bfloat162*>(outH + off) = h;
                    __nv_bfloat162 l;
                    l.x = __float2bfloat16(v0 - __bfloat162float(h.x));
                    l.y = __float2bfloat16(v1 - __bfloat162float(h.y));
                    *reinterpret_cast<__nv_bfloat162*>(outL + off) = l;
                } else if (EPI == 1) {
                    float2 o; o.x = v0; o.y = v1;
                    *reinterpret_cast<float2*>(outF + off) = o;
                } else {
                    float2 o;
                    o.x = 1.f / (1.f + __expf(-v0));
                    o.y = 1.f / (1.f + __expf(-v1));
                    *reinterpret_cast<float2*>(outF + off) = o;
                }
            }
        }
    }
}

// ---------------- exact per-row top-64 threshold (radix binary search) ----------------
// Matches reference semantics exactly: keep h >= (64th largest), ties included.
__global__ void topk_kernel(const float* __restrict__ H, __nv_bfloat16* __restrict__ out) {
    int row = blockIdx.x;
    const float* h = H + (size_t)row * HID;
    int tid = threadIdx.x;  // 256 threads, 8 elems each

    float vals[8];
    unsigned keys[8];
    #pragma unroll
    for (int j = 0; j < 8; j++) {
        float v = h[tid + 256 * j];
        vals[j] = v;
        unsigned u = __float_as_uint(v);
        keys[j] = (u & 0x80000000u) ? ~u : (u | 0x80000000u);  // monotone float->uint
    }

    __shared__ int cnts[32];
    if (tid < 32) cnts[tid] = 0;
    __syncthreads();

    unsigned lo = 0u, hi = 0xFFFFFFFFu;
    // invariant: count(key >= lo) >= 64, count(key >= hi+1) < 64
    for (int it = 0; it < 32; ++it) {
        unsigned mid = lo + ((hi - lo) >> 1) + ((hi - lo) & 1u);  // ceil midpoint
        int c = 0;
        #pragma unroll
        for (int j = 0; j < 8; j++) c += (keys[j] >= mid) ? 1 : 0;
        #pragma unroll
        for (int o = 16; o > 0; o >>= 1) c += __shfl_xor_sync(0xffffffffu, c, o);
        if ((tid & 31) == 0) atomicAdd(&cnts[it], c);
        __syncthreads();
        int total = cnts[it];
        if (total >= 64) lo = mid; else hi = mid - 1u;
    }
    // lo == key of 64th largest value
    size_t base = (size_t)row * HID + tid;
    #pragma unroll
    for (int j = 0; j < 8; j++) {
        __nv_bfloat16 o = (keys[j] >= lo) ? __float2bfloat16(vals[j]) : __float2bfloat16(0.0f);
        out[base + 256 * j] = o;
    }
}

// ---------------- launch ----------------
extern "C" void kernel_launch(void* const* d_in, const int* in_sizes, int n_in,
                              void* d_out, int out_size) {
    (void)in_sizes; (void)n_in; (void)out_size;
    const float* X  = (const float*)d_in[0];
    const float* W1 = (const float*)d_in[1];
    const float* b1 = (const float*)d_in[2];
    const float* W2 = (const float*)d_in[3];
    const float* b2 = (const float*)d_in[4];
    const float* W3 = (const float*)d_in[5];
    const float* b3 = (const float*)d_in[6];
    float* out = (float*)d_out;

    void *xh, *xl, *w1h, *w1l, *w2h, *w2l, *w3h, *h1h, *h1l, *h2, *h2s;
    cudaGetSymbolAddress(&xh,  g_Xh);  cudaGetSymbolAddress(&xl,  g_Xl);
    cudaGetSymbolAddress(&w1h, g_W1h); cudaGetSymbolAddress(&w1l, g_W1l);
    cudaGetSymbolAddress(&w2h, g_W2h); cudaGetSymbolAddress(&w2l, g_W2l);
    cudaGetSymbolAddress(&w3h, g_W3h);
    cudaGetSymbolAddress(&h1h, g_H1h); cudaGetSymbolAddress(&h1l, g_H1l);
    cudaGetSymbolAddress(&h2,  g_H2);  cudaGetSymbolAddress(&h2s, g_H2s);

    constexpr int SMEM3 = (2 * (128 * 40) + 2 * (32 * 136)) * 2 * 2;  // 75776 B
    constexpr int SMEM1 = ((128 * 40) + (32 * 136)) * 2 * 2;          // 37888 B
    cudaFuncSetAttribute(gemm_bf16<3, 0>, cudaFuncAttributeMaxDynamicSharedMemorySize, SMEM3);
    cudaFuncSetAttribute(gemm_bf16<3, 1>, cudaFuncAttributeMaxDynamicSharedMemorySize, SMEM3);
    cudaFuncSetAttribute(gemm_bf16<1, 2>, cudaFuncAttributeMaxDynamicSharedMemorySize, SMEM1);

    // precision splits (deterministic every call; no caching)
    split_kernel<true ><<<2048, 256>>>((const float4*)X,  (__nv_bfloat162*)xh,  (__nv_bfloat162*)xl,
                                       (int)((size_t)BATCH * DIN / 4));
    split_kernel<true ><<<1024, 256>>>((const float4*)W1, (__nv_bfloat162*)w1h, (__nv_bfloat162*)w1l,
                                       DIN * HID / 4);
    split_kernel<true ><<<512,  256>>>((const float4*)W2, (__nv_bfloat162*)w2h, (__nv_bfloat162*)w2l,
                                       HID * HID / 4);
    split_kernel<false><<<1024, 256>>>((const float4*)W3, (__nv_bfloat162*)w3h, nullptr,
                                       HID * DIN / 4);

    dim3 g12(HID / 128, BATCH / 128);  // (16, 64)
    gemm_bf16<3, 0><<<g12, 256, SMEM3>>>(
        (const __nv_bfloat16*)xh, (const __nv_bfloat16*)xl,
        (const __nv_bfloat16*)w1h, (const __nv_bfloat16*)w1l,
        b1, BATCH, HID, DIN,
        nullptr, (__nv_bfloat16*)h1h, (__nv_bfloat16*)h1l);

    gemm_bf16<3, 1><<<g12, 256, SMEM3>>>(
        (const __nv_bfloat16*)h1h, (const __nv_bfloat16*)h1l,
        (const __nv_bfloat16*)w2h, (const __nv_bfloat16*)w2l,
        b2, BATCH, HID, HID,
        (float*)h2, nullptr, nullptr);

    topk_kernel<<<BATCH, 256>>>((const float*)h2, (__nv_bfloat16*)h2s);

    dim3 g3(DIN / 128, BATCH / 128);  // (96, 64)
    gemm_bf16<1, 2><<<g3, 256, SMEM1>>>(
        (const __nv_bfloat16*)h2s, nullptr,
        (const __nv_bfloat16*)w3h, nullptr,
        b3, BATCH, DIN, HID,
        out, nullptr, nullptr);
}

// round 5
// speedup vs baseline: 1.1838x; 1.1838x over previous
#include <cuda_runtime.h>
#include <cuda_bf16.h>
#include <cstdint>
#include <cstddef>

#define BATCH 8192
#define DIN   12288
#define HID   2048

using bf16 = __nv_bfloat16;

// ---------------- static device scratch (no allocations allowed) ----------------
__device__ bf16  g_Xh [(size_t)BATCH * DIN];
__device__ bf16  g_Xl [(size_t)BATCH * DIN];
__device__ bf16  g_W1h[(size_t)DIN * HID];
__device__ bf16  g_W1l[(size_t)DIN * HID];
__device__ bf16  g_W2h[(size_t)HID * HID];
__device__ bf16  g_W2l[(size_t)HID * HID];
__device__ bf16  g_W3h[(size_t)HID * DIN];
__device__ bf16  g_H1h[(size_t)BATCH * HID];
__device__ bf16  g_H1l[(size_t)BATCH * HID];
__device__ float g_H2 [(size_t)BATCH * HID];
__device__ bf16  g_H2s[(size_t)BATCH * HID];

// ---------------- helpers ----------------
__device__ __forceinline__ unsigned sptr(const void* p) {
    return (unsigned)__cvta_generic_to_shared(p);
}
__device__ __forceinline__ void ldsm4(unsigned &r0, unsigned &r1, unsigned &r2, unsigned &r3, unsigned a) {
    asm volatile("ldmatrix.sync.aligned.m8n8.x4.shared.b16 {%0,%1,%2,%3}, [%4];\n"
                 : "=r"(r0), "=r"(r1), "=r"(r2), "=r"(r3) : "r"(a));
}
__device__ __forceinline__ void ldsm4t(unsigned &r0, unsigned &r1, unsigned &r2, unsigned &r3, unsigned a) {
    asm volatile("ldmatrix.sync.aligned.m8n8.x4.trans.shared.b16 {%0,%1,%2,%3}, [%4];\n"
                 : "=r"(r0), "=r"(r1), "=r"(r2), "=r"(r3) : "r"(a));
}
__device__ __forceinline__ void mma16816(float* d, const unsigned* a, const unsigned* b) {
    asm volatile("mma.sync.aligned.m16n8k16.row.col.f32.bf16.bf16.f32 "
                 "{%0,%1,%2,%3}, {%4,%5,%6,%7}, {%8,%9}, {%0,%1,%2,%3};\n"
                 : "+f"(d[0]), "+f"(d[1]), "+f"(d[2]), "+f"(d[3])
                 : "r"(a[0]), "r"(a[1]), "r"(a[2]), "r"(a[3]), "r"(b[0]), "r"(b[1]));
}
template<int N>
__device__ __forceinline__ void cpwait() {
    asm volatile("cp.async.wait_group %0;\n" :: "n"(N) : "memory");
}
__device__ __forceinline__ void cpcommit() {
    asm volatile("cp.async.commit_group;\n" ::: "memory");
}
__device__ __forceinline__ void cpasync16(unsigned d, const void* g) {
    asm volatile("cp.async.cg.shared.global [%0], [%1], 16;\n" :: "r"(d), "l"(g));
}

// ---------------- fp32 -> bf16 (hi, lo) split ----------------
template<bool HASLO>
__global__ void split_kernel(const float4* __restrict__ in,
                             __nv_bfloat162* __restrict__ hi,
                             __nv_bfloat162* __restrict__ lo, int n4) {
    int stride = gridDim.x * blockDim.x;
    for (int i = blockIdx.x * blockDim.x + threadIdx.x; i < n4; i += stride) {
        float4 v = in[i];
        bf16 h0 = __float2bfloat16(v.x), h1 = __float2bfloat16(v.y);
        bf16 h2 = __float2bfloat16(v.z), h3 = __float2bfloat16(v.w);
        __nv_bfloat162 a; a.x = h0; a.y = h1;
        __nv_bfloat162 b; b.x = h2; b.y = h3;
        hi[2 * i] = a; hi[2 * i + 1] = b;
        if (HASLO) {
            __nv_bfloat162 c, d;
            c.x = __float2bfloat16(v.x - __bfloat162float(h0));
            c.y = __float2bfloat16(v.y - __bfloat162float(h1));
            d.x = __float2bfloat16(v.z - __bfloat162float(h2));
            d.y = __float2bfloat16(v.w - __bfloat162float(h3));
            lo[2 * i] = c; lo[2 * i + 1] = d;
        }
    }
}

// ---------------- GEMM: C[M,N] = A[M,K] * B[K,N] (+bias, epilogue) ----------------
// SPLIT==3: Ootomo (Ah*Bh + Al*Bh + Ah*Bl), fp32 accum.  SPLIT==1: plain bf16.
// EPI: 0 relu -> (hi,lo) bf16 split; 1 fp32; 2 sigmoid fp32.
// Multistage cp.async pipeline, single __syncthreads per k-iter, frag reuse.
template<int SPLIT, int EPI, int STAGES>
__global__ void __launch_bounds__(256, (SPLIT == 1) ? 2 : 1)
gemm_bf16(const bf16* __restrict__ Ah, const bf16* __restrict__ Al,
          const bf16* __restrict__ Bh, const bf16* __restrict__ Bl,
          const float* __restrict__ bias, int M, int N, int K,
          float* __restrict__ outF, bf16* __restrict__ outH, bf16* __restrict__ outL)
{
    constexpr int AP = 128 * 40;      // A part elems (32 cols + 8 pad per row)
    constexpr int BP = 32 * 136;      // B part elems (128 cols + 8 pad per row)
    constexpr int PARTS = (SPLIT == 3) ? 2 : 1;
    constexpr int STAGE = (AP + BP) * PARTS;
    extern __shared__ bf16 smbuf[];

    const int tid  = threadIdx.x;
    const int bm   = blockIdx.y * 128;
    const int bn   = blockIdx.x * 128;
    const int lane = tid & 31;
    const int warp = tid >> 5;
    const int wm   = warp & 3;   // 4 warps along M (32 rows each)
    const int wn   = warp >> 2;  // 2 warps along N (64 cols each)

    float acc[2][8][4];
    #pragma unroll
    for (int i = 0; i < 2; i++)
        #pragma unroll
        for (int j = 0; j < 8; j++)
            #pragma unroll
            for (int k = 0; k < 4; k++) acc[i][j][k] = 0.f;

    auto cpA = [&](const bf16* src, bf16* dst, int k0) {
        #pragma unroll
        for (int i = 0; i < 2; i++) {
            int c = tid + i * 256;
            int row = c >> 2, seg = c & 3;
            cpasync16(sptr(dst + row * 40 + seg * 8),
                      src + (size_t)(bm + row) * K + (k0 + seg * 8));
        }
    };
    auto cpB = [&](const bf16* src, bf16* dst, int k0) {
        #pragma unroll
        for (int i = 0; i < 2; i++) {
            int c = tid + i * 256;
            int row = c >> 4, seg = c & 15;
            cpasync16(sptr(dst + row * 136 + seg * 8),
                      src + (size_t)(k0 + row) * N + (bn + seg * 8));
        }
    };
    auto issue = [&](int kt) {
        int k0 = kt * 32;
        bf16* base = smbuf + (size_t)(kt % STAGES) * STAGE;
        cpA(Ah, base, k0);
        if (SPLIT == 3) cpA(Al, base + AP, k0);
        cpB(Bh, base + AP * PARTS, k0);
        if (SPLIT == 3) cpB(Bl, base + AP * PARTS + BP, k0);
        cpcommit();
    };

    const int KT = K / 32;
    #pragma unroll
    for (int s = 0; s < STAGES - 1; s++) issue(s);

    for (int kt = 0; kt < KT; ++kt) {
        if (kt + 1 < KT) cpwait<STAGES - 2>(); else cpwait<0>();
        __syncthreads();

        bf16* base = smbuf + (size_t)(kt % STAGES) * STAGE;
        const bf16* Ash = base;
        const bf16* Asl = base + AP;
        const bf16* Bsh = base + AP * PARTS;
        const bf16* Bsl = Bsh + BP;

        #pragma unroll
        for (int ks = 0; ks < 2; ++ks) {
            const int arow = wm * 32 + (lane & 15);
            const int acol = ks * 16 + (lane >> 4) * 8;
            const int brow = ks * 16 + (lane & 7) + 8 * ((lane >> 3) & 1);
            const int bcol = wn * 64 + 8 * (lane >> 4);

            unsigned ah[2][4];
            #pragma unroll
            for (int mi = 0; mi < 2; mi++)
                ldsm4(ah[mi][0], ah[mi][1], ah[mi][2], ah[mi][3],
                      sptr(Ash + (size_t)(arow + mi * 16) * 40 + acol));
            unsigned bh[8][2];
            #pragma unroll
            for (int np = 0; np < 4; np++) {
                unsigned r0, r1, r2, r3;
                ldsm4t(r0, r1, r2, r3, sptr(Bsh + (size_t)brow * 136 + bcol + np * 16));
                bh[2 * np][0] = r0; bh[2 * np][1] = r1;
                bh[2 * np + 1][0] = r2; bh[2 * np + 1][1] = r3;
            }
            #pragma unroll
            for (int mi = 0; mi < 2; mi++)
                #pragma unroll
                for (int ni = 0; ni < 8; ni++)
                    mma16816(acc[mi][ni], ah[mi], bh[ni]);

            if (SPLIT == 3) {
                // al * bh  (reuse bh frags)
                unsigned al_[2][4];
                #pragma unroll
                for (int mi = 0; mi < 2; mi++)
                    ldsm4(al_[mi][0], al_[mi][1], al_[mi][2], al_[mi][3],
                          sptr(Asl + (size_t)(arow + mi * 16) * 40 + acol));
                #pragma unroll
                for (int mi = 0; mi < 2; mi++)
                    #pragma unroll
                    for (int ni = 0; ni < 8; ni++)
                        mma16816(acc[mi][ni], al_[mi], bh[ni]);
                // ah * bl  (reuse ah frags)
                unsigned bl_[8][2];
                #pragma unroll
                for (int np = 0; np < 4; np++) {
                    unsigned r0, r1, r2, r3;
                    ldsm4t(r0, r1, r2, r3, sptr(Bsl + (size_t)brow * 136 + bcol + np * 16));
                    bl_[2 * np][0] = r0; bl_[2 * np][1] = r1;
                    bl_[2 * np + 1][0] = r2; bl_[2 * np + 1][1] = r3;
                }
                #pragma unroll
                for (int mi = 0; mi < 2; mi++)
                    #pragma unroll
                    for (int ni = 0; ni < 8; ni++)
                        mma16816(acc[mi][ni], ah[mi], bl_[ni]);
            }
        }

        if (kt + STAGES - 1 < KT) issue(kt + STAGES - 1);
    }

    // ---------------- epilogue ----------------
    #pragma unroll
    for (int mi = 0; mi < 2; mi++) {
        #pragma unroll
        for (int ni = 0; ni < 8; ni++) {
            int r = bm + wm * 32 + mi * 16 + (lane >> 2);
            int c = bn + wn * 64 + ni * 8 + (lane & 3) * 2;
            float bb0 = bias[c], bb1 = bias[c + 1];
            #pragma unroll
            for (int half = 0; half < 2; ++half) {
                int rr = r + half * 8;
                float v0 = acc[mi][ni][2 * half + 0] + bb0;
                float v1 = acc[mi][ni][2 * half + 1] + bb1;
                size_t off = (size_t)rr * N + c;
                if (EPI == 0) {
                    v0 = fmaxf(v0, 0.f); v1 = fmaxf(v1, 0.f);
                    __nv_bfloat162 h; h.x = __float2bfloat16(v0); h.y = __float2bfloat16(v1);
                    *reinterpret_cast<__nv_bfloat162*>(outH + off) = h;
                    __nv_bfloat162 l;
                    l.x = __float2bfloat16(v0 - __bfloat162float(h.x));
                    l.y = __float2bfloat16(v1 - __bfloat162float(h.y));
                    *reinterpret_cast<__nv_bfloat162*>(outL + off) = l;
                } else if (EPI == 1) {
                    float2 o; o.x = v0; o.y = v1;
                    *reinterpret_cast<float2*>(outF + off) = o;
                } else {
                    float2 o;
                    o.x = 1.f / (1.f + __expf(-v0));
                    o.y = 1.f / (1.f + __expf(-v1));
                    *reinterpret_cast<float2*>(outF + off) = o;
                }
            }
        }
    }
}

// ---------------- exact per-row top-64 threshold (radix binary search) ----------------
__global__ void topk_kernel(const float* __restrict__ H, bf16* __restrict__ out) {
    int row = blockIdx.x;
    const float* h = H + (size_t)row * HID;
    int tid = threadIdx.x;  // 256 threads, 8 elems each

    float vals[8];
    unsigned keys[8];
    #pragma unroll
    for (int j = 0; j < 8; j++) {
        float v = h[tid + 256 * j];
        vals[j] = v;
        unsigned u = __float_as_uint(v);
        keys[j] = (u & 0x80000000u) ? ~u : (u | 0x80000000u);
    }

    __shared__ int cnts[32];
    if (tid < 32) cnts[tid] = 0;
    __syncthreads();

    unsigned lo = 0u, hi = 0xFFFFFFFFu;
    for (int it = 0; it < 32; ++it) {
        unsigned mid = lo + ((hi - lo) >> 1) + ((hi - lo) & 1u);
        int c = 0;
        #pragma unroll
        for (int j = 0; j < 8; j++) c += (keys[j] >= mid) ? 1 : 0;
        #pragma unroll
        for (int o = 16; o > 0; o >>= 1) c += __shfl_xor_sync(0xffffffffu, c, o);
        if ((tid & 31) == 0) atomicAdd(&cnts[it], c);
        __syncthreads();
        int total = cnts[it];
        if (total >= 64) lo = mid; else hi = mid - 1u;
    }
    size_t base = (size_t)row * HID + tid;
    #pragma unroll
    for (int j = 0; j < 8; j++) {
        out[base + 256 * j] = (keys[j] >= lo) ? __float2bfloat16(vals[j]) : __float2bfloat16(0.0f);
    }
}

// ---------------- launch ----------------
extern "C" void kernel_launch(void* const* d_in, const int* in_sizes, int n_in,
                              void* d_out, int out_size) {
    (void)in_sizes; (void)n_in; (void)out_size;
    const float* X  = (const float*)d_in[0];
    const float* W1 = (const float*)d_in[1];
    const float* b1 = (const float*)d_in[2];
    const float* W2 = (const float*)d_in[3];
    const float* b2 = (const float*)d_in[4];
    const float* W3 = (const float*)d_in[5];
    const float* b3 = (const float*)d_in[6];
    float* out = (float*)d_out;

    void *xh, *xl, *w1h, *w1l, *w2h, *w2l, *w3h, *h1h, *h1l, *h2, *h2s;
    cudaGetSymbolAddress(&xh,  g_Xh);  cudaGetSymbolAddress(&xl,  g_Xl);
    cudaGetSymbolAddress(&w1h, g_W1h); cudaGetSymbolAddress(&w1l, g_W1l);
    cudaGetSymbolAddress(&w2h, g_W2h); cudaGetSymbolAddress(&w2l, g_W2l);
    cudaGetSymbolAddress(&w3h, g_W3h);
    cudaGetSymbolAddress(&h1h, g_H1h); cudaGetSymbolAddress(&h1l, g_H1l);
    cudaGetSymbolAddress(&h2,  g_H2);  cudaGetSymbolAddress(&h2s, g_H2s);

    constexpr int STAGE3 = ((128 * 40) + (32 * 136)) * 2;  // split-3 stage elems
    constexpr int STAGE1 = ((128 * 40) + (32 * 136));      // split-1 stage elems
    constexpr int SMEM3 = STAGE3 * 3 * 2;                  // 113664 B (3 stages)
    constexpr int SMEM1 = STAGE1 * 4 * 2;                  // 75776 B  (4 stages)
    cudaFuncSetAttribute(gemm_bf16<3, 0, 3>, cudaFuncAttributeMaxDynamicSharedMemorySize, SMEM3);
    cudaFuncSetAttribute(gemm_bf16<3, 1, 3>, cudaFuncAttributeMaxDynamicSharedMemorySize, SMEM3);
    cudaFuncSetAttribute(gemm_bf16<1, 2, 4>, cudaFuncAttributeMaxDynamicSharedMemorySize, SMEM1);

    // precision splits
    split_kernel<true ><<<2048, 256>>>((const float4*)X,  (__nv_bfloat162*)xh,  (__nv_bfloat162*)xl,
                                       (int)((size_t)BATCH * DIN / 4));
    split_kernel<true ><<<1024, 256>>>((const float4*)W1, (__nv_bfloat162*)w1h, (__nv_bfloat162*)w1l,
                                       DIN * HID / 4);
    split_kernel<true ><<<512,  256>>>((const float4*)W2, (__nv_bfloat162*)w2h, (__nv_bfloat162*)w2l,
                                       HID * HID / 4);
    split_kernel<false><<<1024, 256>>>((const float4*)W3, (__nv_bfloat162*)w3h, nullptr,
                                       HID * DIN / 4);

    dim3 g12(HID / 128, BATCH / 128);  // (16, 64)
    gemm_bf16<3, 0, 3><<<g12, 256, SMEM3>>>(
        (const bf16*)xh, (const bf16*)xl, (const bf16*)w1h, (const bf16*)w1l,
        b1, BATCH, HID, DIN,
        nullptr, (bf16*)h1h, (bf16*)h1l);

    gemm_bf16<3, 1, 3><<<g12, 256, SMEM3>>>(
        (const bf16*)h1h, (const bf16*)h1l, (const bf16*)w2h, (const bf16*)w2l,
        b2, BATCH, HID, HID,
        (float*)h2, nullptr, nullptr);

    topk_kernel<<<BATCH, 256>>>((const float*)h2, (bf16*)h2s);

    dim3 g3(DIN / 128, BATCH / 128);  // (96, 64)
    gemm_bf16<1, 2, 4><<<g3, 256, SMEM1>>>(
        (const bf16*)h2s, nullptr, (const bf16*)w3h, nullptr,
        b3, BATCH, DIN, HID,
        out, nullptr, nullptr);
}